// round 5
// baseline (speedup 1.0000x reference)
#include <cuda_runtime.h>
#include <cuda_bf16.h>

// Distance_26379689132772: dense radius_graph over N=8192 atoms, 128 atoms/mol.
// Output layout (f32): [0, N*N)       edge_weight (row-major [i,j])
//                      [N*N, 2*N*N)  mask as 0.0/1.0
//
// Pure HBM-store-bound (512 MB written). Flat launch; each thread produces
// 8 consecutive floats per plane and stores them with one 256-bit STG
// (st.global.v8.b32, sm_100a), so each warp writes one contiguous 1KB run
// per plane per instruction.

#define NATOMS 8192
#define CUT_HI 5.0f
#define NN     (NATOMS * NATOMS)       // 67,108,864 floats per plane

__device__ __forceinline__ void stg256(float* p, const float* v)
{
    asm volatile(
        "st.global.v8.b32 [%0], {%1,%2,%3,%4,%5,%6,%7,%8};"
        :: "l"(p),
           "r"(__float_as_uint(v[0])), "r"(__float_as_uint(v[1])),
           "r"(__float_as_uint(v[2])), "r"(__float_as_uint(v[3])),
           "r"(__float_as_uint(v[4])), "r"(__float_as_uint(v[5])),
           "r"(__float_as_uint(v[6])), "r"(__float_as_uint(v[7]))
        : "memory");
}

__global__ __launch_bounds__(256)
void dist_kernel(const float* __restrict__ pos,
                 const int*   __restrict__ batch,
                 float*       __restrict__ out)
{
    // One thread per 8 consecutive floats of one row. NN/8 = 8,388,608 octs.
    unsigned oct = blockIdx.x * 256u + threadIdx.x;
    unsigned base = oct << 3;                 // float offset within plane
    int i = (int)(base >> 13);                // base / 8192
    int j = (int)(base & 8191u);              // j..j+7, 8-aligned

    float w[8] = {0.f,0.f,0.f,0.f,0.f,0.f,0.f,0.f};
    float m[8] = {0.f,0.f,0.f,0.f,0.f,0.f,0.f,0.f};

    int bi = __ldg(batch + i);
    int bj = __ldg(batch + j);                // j..j+7 share one 128-block

    if (bi == bj) {
        float xi = __ldg(pos + 3 * i + 0);
        float yi = __ldg(pos + 3 * i + 1);
        float zi = __ldg(pos + 3 * i + 2);
        float sqi = xi * xi + yi * yi + zi * zi;

        #pragma unroll
        for (int k = 0; k < 8; k++) {
            int jj = j + k;
            float xj = __ldg(pos + 3 * jj + 0);
            float yj = __ldg(pos + 3 * jj + 1);
            float zj = __ldg(pos + 3 * jj + 2);
            float sqj = xj * xj + yj * yj + zj * zj;
            // Gram trick, matching the reference's arithmetic path.
            float d2 = sqi + sqj - 2.0f * (xi * xj + yi * yj + zi * zj);
            d2 = fmaxf(d2, 0.0f);
            float d = (d2 > 0.0f) ? sqrtf(d2) : 0.0f;
            bool mask = (i != jj) && (d <= CUT_HI);
            w[k] = mask ? d : 0.0f;
            m[k] = mask ? 1.0f : 0.0f;
        }
    }

    stg256(out + base,      w);
    stg256(out + NN + base, m);
}

extern "C" void kernel_launch(void* const* d_in, const int* in_sizes, int n_in,
                              void* d_out, int out_size)
{
    const float* pos   = (const float*)d_in[0];
    const int*   batch = (const int*)d_in[1];
    float*       out   = (float*)d_out;

    // NN/8 threads, 256 per block -> 32768 blocks.
    dist_kernel<<<NN / 8 / 256, 256>>>(pos, batch, out);
}

// round 7
// speedup vs baseline: 1.0004x; 1.0004x over previous
#include <cuda_runtime.h>
#include <cuda_bf16.h>

// Distance_26379689132772: dense radius_graph over N=8192 atoms, 128 atoms/mol.
// Output layout (f32): [0, N*N)       edge_weight (row-major [i,j])
//                      [N*N, 2*N*N)  mask as 0.0/1.0
//
// Pure HBM-store-bound (512 MB written). Each BLOCK writes one contiguous
// 16KB chunk of exactly ONE plane (even block -> weight, odd -> mask), so the
// DRAM controllers see half as many concurrent write streams. Distance math
// is recomputed in mask blocks (compute pipes are ~idle; this is free).

#define NATOMS 8192
#define CUT_HI 5.0f
#define NN     (NATOMS * NATOMS)       // 67,108,864 floats per plane

__device__ __forceinline__ void stg256(float* p, const float* v)
{
    asm volatile(
        "st.global.v8.b32 [%0], {%1,%2,%3,%4,%5,%6,%7,%8};"
        :: "l"(p),
           "r"(__float_as_uint(v[0])), "r"(__float_as_uint(v[1])),
           "r"(__float_as_uint(v[2])), "r"(__float_as_uint(v[3])),
           "r"(__float_as_uint(v[4])), "r"(__float_as_uint(v[5])),
           "r"(__float_as_uint(v[6])), "r"(__float_as_uint(v[7]))
        : "memory");
}

// Compute 8 consecutive weight/mask values starting at float offset `base`
// (8-aligned) within the [N,N] plane. want_w selects which value is emitted.
__device__ __forceinline__ void compute_oct(const float* __restrict__ pos,
                                            const int*   __restrict__ batch,
                                            unsigned base, bool want_w,
                                            float* __restrict__ v)
{
    int i = (int)(base >> 13);            // base / 8192
    int j = (int)(base & 8191u);          // j..j+7, 8-aligned

    #pragma unroll
    for (int k = 0; k < 8; k++) v[k] = 0.f;

    int bi = __ldg(batch + i);
    int bj = __ldg(batch + j);            // j..j+7 share one 128-block

    if (bi == bj) {
        float xi = __ldg(pos + 3 * i + 0);
        float yi = __ldg(pos + 3 * i + 1);
        float zi = __ldg(pos + 3 * i + 2);
        float sqi = xi * xi + yi * yi + zi * zi;

        #pragma unroll
        for (int k = 0; k < 8; k++) {
            int jj = j + k;
            float xj = __ldg(pos + 3 * jj + 0);
            float yj = __ldg(pos + 3 * jj + 1);
            float zj = __ldg(pos + 3 * jj + 2);
            float sqj = xj * xj + yj * yj + zj * zj;
            // Gram trick, matching the reference's arithmetic path.
            float d2 = sqi + sqj - 2.0f * (xi * xj + yi * yj + zi * zj);
            d2 = fmaxf(d2, 0.0f);
            float d = (d2 > 0.0f) ? sqrtf(d2) : 0.0f;
            bool mask = (i != jj) && (d <= CUT_HI);
            v[k] = mask ? (want_w ? d : 1.0f) : 0.0f;
        }
    }
}

__global__ __launch_bounds__(256)
void dist_kernel(const float* __restrict__ pos,
                 const int*   __restrict__ batch,
                 float*       __restrict__ out)
{
    // Even block -> weight plane, odd block -> mask plane.
    unsigned chunk = blockIdx.x >> 1;          // 16384 chunks per plane
    bool want_w    = (blockIdx.x & 1u) == 0u;
    float* plane   = want_w ? out : out + NN;

    // Block covers 4096 consecutive floats (16KB) of its plane.
    // Thread t writes floats [cb + t*8, +8) and [cb + 2048 + t*8, +8):
    // both warp-contiguous 1KB runs.
    unsigned cb = chunk * 4096u;
    unsigned o0 = cb + threadIdx.x * 8u;
    unsigned o1 = o0 + 2048u;

    float v0[8], v1[8];
    compute_oct(pos, batch, o0, want_w, v0);
    compute_oct(pos, batch, o1, want_w, v1);

    stg256(plane + o0, v0);
    stg256(plane + o1, v1);
}

extern "C" void kernel_launch(void* const* d_in, const int* in_sizes, int n_in,
                              void* d_out, int out_size)
{
    const float* pos   = (const float*)d_in[0];
    const int*   batch = (const int*)d_in[1];
    float*       out   = (float*)d_out;

    // 2 planes * NN/4096 chunks = 32768 blocks, 256 threads each.
    dist_kernel<<<2 * (NN / 4096), 256>>>(pos, batch, out);
}